// round 12
// baseline (speedup 1.0000x reference)
#include <cuda_runtime.h>
#include <cuda_fp16.h>
#include <cstdint>
#include <math.h>

#define NN 100000
#define NE 1600000
#define FD 128
#define NG 128
#define GF 32

#define B_SCALE 32.0f
#define B_INV   (1.0f / 32.0f)

// ---------------- scratch (device globals; no allocations allowed) ----------
__device__ __align__(16) unsigned char g_U[(size_t)NN * 256]; // [X|AGG] e4m3
__device__ __align__(16) unsigned char g_B[2 * 128 * 256];    // W^T e4m3 (x32)
__device__ __align__(16) float g_h1[(size_t)NN * FD];
__device__ int g_deg[NN];
__device__ int g_rowptr[NN + 1];
__device__ int g_fill[NN];
__device__ int g_col[NE];
__device__ int g_bsum[128];
__device__ int g_bpre[128];
__device__ int g_scnt;
__device__ int g_sready;

// ---------------- small helpers ---------------------------------------------
// pack: byte0 = lo, byte1 = hi
__device__ __forceinline__ unsigned short f2e4m3x2(float hi, float lo) {
    unsigned short r;
    asm("cvt.rn.satfinite.e4m3x2.f32 %0, %1, %2;" : "=h"(r) : "f"(hi), "f"(lo));
    return r;
}
__device__ __forceinline__ float2 e4m3x2f2(unsigned short u) {
    uint32_t h2;
    asm("cvt.rn.f16x2.e4m3x2 %0, %1;" : "=r"(h2) : "h"(u));
    return __half22float2(*(__half2*)&h2);
}

__device__ __forceinline__ uint32_t smem_u32(const void* p) {
    uint32_t a;
    asm("{ .reg .u64 t; cvta.to.shared.u64 t, %1; cvt.u32.u64 %0, t; }"
        : "=r"(a) : "l"(p));
    return a;
}

__device__ __forceinline__ void ldsm4(uint32_t* r, uint32_t addr) {
    asm volatile("ldmatrix.sync.aligned.m8n8.x4.shared.b16 {%0,%1,%2,%3}, [%4];"
                 : "=r"(r[0]), "=r"(r[1]), "=r"(r[2]), "=r"(r[3]) : "r"(addr));
}
__device__ __forceinline__ void ldsm2(uint32_t* r, uint32_t addr) {
    asm volatile("ldmatrix.sync.aligned.m8n8.x2.shared.b16 {%0,%1}, [%2];"
                 : "=r"(r[0]), "=r"(r[1]) : "r"(addr));
}
__device__ __forceinline__ void mma_fp8(float* c, const uint32_t* a, const uint32_t* b) {
    asm volatile(
        "mma.sync.aligned.m16n8k32.row.col.f32.e4m3.e4m3.f32 "
        "{%0,%1,%2,%3}, {%4,%5,%6,%7}, {%8,%9}, {%0,%1,%2,%3};"
        : "+f"(c[0]), "+f"(c[1]), "+f"(c[2]), "+f"(c[3])
        : "r"(a[0]), "r"(a[1]), "r"(a[2]), "r"(a[3]), "r"(b[0]), "r"(b[1]));
}

// ---------------- fused prep: zero CSR state + weight fp8 + x fp8 -----------
__global__ void k_prep(const float* __restrict__ X,
                       const float* __restrict__ Wr0, const float* __restrict__ Wl0,
                       const float* __restrict__ Wr1, const float* __restrict__ Wl1) {
    int i = blockIdx.x * 256 + threadIdx.x;
    if (i < NN * 32) {                               // split x -> e4m3 U cols 0..127
        float4 v = ((const float4*)X)[i];
        int node = i >> 5, q = (i & 31) * 4;
        uint32_t lo = f2e4m3x2(v.y, v.x);
        uint32_t hi = f2e4m3x2(v.w, v.z);
        *(uint32_t*)(g_U + (size_t)node * 256 + q) = lo | (hi << 16);
    }
    if (i < 65536) {                                 // weights -> e4m3 (x32)
        int L = i >> 15;
        int rem = i & 32767;
        int k = rem >> 7, n = rem & 127;
        const float* Wr = L ? Wr1 : Wr0;
        const float* Wl = L ? Wl1 : Wl0;
        float v = ((k < FD) ? Wr[k * FD + n] : Wl[(k - FD) * FD + n]) * B_SCALE;
        unsigned short p = f2e4m3x2(0.f, v);
        g_B[L * 32768 + n * 256 + k] = (unsigned char)(p & 0xFF);
    }
    if (i < NN) { g_deg[i] = 0; g_fill[i] = 0; }
    if (i == 0) { g_scnt = 0; g_sready = 0; }
}

// ---------------- CSR: histogram ---------------------------------------------
__global__ void k_hist(const int* __restrict__ edges) {
    int e = blockIdx.x * blockDim.x + threadIdx.x;
    if (e < NE) atomicAdd(&g_deg[edges[NE + e]], 1);
}

// ---------------- CSR: single-kernel exclusive scan (publish + wait) ---------
#define SCAN_B 1024
__global__ void k_scan() {
    __shared__ int sm[SCAN_B];
    __shared__ int bpre;
    int bid = blockIdx.x, tid = threadIdx.x;
    int i = bid * SCAN_B + tid;
    int v = (i < NN) ? g_deg[i] : 0;
    sm[tid] = v;
    __syncthreads();
    for (int off = 1; off < SCAN_B; off <<= 1) {
        int t = (tid >= off) ? sm[tid - off] : 0;
        __syncthreads();
        sm[tid] += t;
        __syncthreads();
    }
    if (tid == SCAN_B - 1) {
        g_bsum[bid] = sm[SCAN_B - 1];
        __threadfence();
        int d = atomicAdd(&g_scnt, 1);
        if (d == (int)gridDim.x - 1) {               // last block: scan aggregates
            int acc = 0;
#pragma unroll 4
            for (int j = 0; j < (int)gridDim.x; j++) {
                int t = g_bsum[j];
                g_bpre[j] = acc;
                acc += t;
            }
            __threadfence();
            atomicExch(&g_sready, 1);
        }
    }
    if (tid == 0) {
        while (*((volatile int*)&g_sready) == 0) __nanosleep(64);
        bpre = *((volatile int*)&g_bpre[bid]);
    }
    __syncthreads();
    if (i < NN) g_rowptr[i] = sm[tid] - v + bpre;    // exclusive
    if (i == 0) g_rowptr[NN] = NE;
}

__global__ void k_fillcol(const int* __restrict__ edges) {
    int e = blockIdx.x * blockDim.x + threadIdx.x;
    if (e < NE) {
        int t = edges[NE + e];
        int p = g_rowptr[t] + atomicAdd(&g_fill[t], 1);
        g_col[p] = edges[e];
    }
}

// ---------------- neighbor mean aggregation (e4m3 gather) --------------------
__global__ void k_aggregate() {
    int node = blockIdx.x * 8 + (threadIdx.x >> 5);
    int lane = threadIdx.x & 31;
    if (node >= NN) return;
    int beg = g_rowptr[node], end = g_rowptr[node + 1];
    const uint32_t* Hv = (const uint32_t*)g_U;       // 4 fp8 per lane
    float4 s = make_float4(0.f, 0.f, 0.f, 0.f);
    int e = beg;
    for (; e + 3 < end; e += 4) {
        int i0 = g_col[e], i1 = g_col[e + 1], i2 = g_col[e + 2], i3 = g_col[e + 3];
        uint32_t u0 = Hv[(size_t)i0 * 64 + lane];
        uint32_t u1 = Hv[(size_t)i1 * 64 + lane];
        uint32_t u2 = Hv[(size_t)i2 * 64 + lane];
        uint32_t u3 = Hv[(size_t)i3 * 64 + lane];
        float2 a0 = e4m3x2f2((unsigned short)u0), a1 = e4m3x2f2((unsigned short)(u0 >> 16));
        float2 b0 = e4m3x2f2((unsigned short)u1), b1 = e4m3x2f2((unsigned short)(u1 >> 16));
        float2 c0 = e4m3x2f2((unsigned short)u2), c1 = e4m3x2f2((unsigned short)(u2 >> 16));
        float2 d0 = e4m3x2f2((unsigned short)u3), d1 = e4m3x2f2((unsigned short)(u3 >> 16));
        s.x += (a0.x + b0.x) + (c0.x + d0.x);
        s.y += (a0.y + b0.y) + (c0.y + d0.y);
        s.z += (a1.x + b1.x) + (c1.x + d1.x);
        s.w += (a1.y + b1.y) + (c1.y + d1.y);
    }
    for (; e < end; e++) {
        uint32_t u = Hv[(size_t)g_col[e] * 64 + lane];
        float2 f0 = e4m3x2f2((unsigned short)u), f1 = e4m3x2f2((unsigned short)(u >> 16));
        s.x += f0.x; s.y += f0.y; s.z += f1.x; s.w += f1.y;
    }
    float sc = 1.f / fmaxf((float)(end - beg), 1.f);
    uint32_t lo = f2e4m3x2(s.y * sc, s.x * sc);
    uint32_t hi = f2e4m3x2(s.w * sc, s.z * sc);
    *(uint32_t*)(g_U + (size_t)node * 256 + 128 + lane * 4) = lo | (hi << 16);
}

// ---------------- mma.sync GEMM: e4m3 A x e4m3 B (m16n8k32) -----------------
// CTA: 128 nodes x 128 outs; 8 warps 2(M)x4(N); warp tile 64x32.
// K = 256 fp8 bytes, 2 chunks of 128B; ks step = 32 bytes (k32).
#define TPB 144
#define TILE_B (128 * TPB)                   // 18432 bytes per tile
#define GEMM_SMEM (2 * TILE_B + 512)

__device__ __forceinline__ void load_chunk(unsigned char* dst,
                                           const unsigned char* __restrict__ src,
                                           int row0, int rowmax, int kofs) {
    for (int i = threadIdx.x; i < 1024; i += 256) {  // uint4 units (16 fp8)
        int r = i >> 3, q = i & 7;
        int gr = row0 + r;
        uint4 v = make_uint4(0, 0, 0, 0);
        if (gr < rowmax) v = *(const uint4*)(src + (size_t)gr * 256 + kofs + q * 16);
        *(uint4*)(dst + r * TPB + q * 16) = v;
    }
}

__global__ __launch_bounds__(256, 2) void k_gemm(
    const unsigned char* __restrict__ U, const unsigned char* __restrict__ B,
    const float* __restrict__ bias, float* __restrict__ OUT,
    unsigned char* __restrict__ NU, int relu, int wsplit)
{
    extern __shared__ char smem[];
    unsigned char* sU = (unsigned char*)smem;
    unsigned char* sB = (unsigned char*)(smem + TILE_B);
    float* sbias = (float*)(smem + 2 * TILE_B);

    const int tid = threadIdx.x, wid = tid >> 5, lid = tid & 31;
    const int wm = wid >> 2, wn = wid & 3;
    const int node0 = blockIdx.x * 128;

    if (tid < FD) sbias[tid] = bias[tid];

    float acc[4][4][4];
#pragma unroll
    for (int mt = 0; mt < 4; mt++)
#pragma unroll
        for (int nt = 0; nt < 4; nt++)
#pragma unroll
            for (int j = 0; j < 4; j++) acc[mt][nt][j] = 0.f;

    uint32_t aU = smem_u32(sU), aB = smem_u32(sB);
    const uint32_t a_lane = (uint32_t)((lid & 15) * TPB + ((lid >> 4) << 4));
    const uint32_t b_lane = (uint32_t)((lid & 7) * TPB + (((lid >> 3) & 1) << 4));

    for (int c = 0; c < 2; c++) {
        load_chunk(sU, U, node0, NN, c * 128);
        load_chunk(sB, B, 0, 128, c * 128);
        __syncthreads();
#pragma unroll
        for (int ks = 0; ks < 4; ks++) {
            uint32_t ah[4][4];
#pragma unroll
            for (int mt = 0; mt < 4; mt++) {
                uint32_t roff = (uint32_t)((wm * 64 + mt * 16) * TPB + ks * 32);
                ldsm4(ah[mt], aU + roff + a_lane);
            }
#pragma unroll
            for (int nt = 0; nt < 4; nt++) {
                uint32_t bb[2];
                uint32_t roff = (uint32_t)((wn * 32 + nt * 8) * TPB + ks * 32);
                ldsm2(bb, aB + roff + b_lane);
#pragma unroll
                for (int mt = 0; mt < 4; mt++)
                    mma_fp8(acc[mt][nt], ah[mt], bb);
            }
        }
        __syncthreads();
    }

    // epilogue: c-fragment (row = t/4 [+8], col = 2*(t%4) [+1])
    const int tq = lid >> 2, tr = lid & 3;
#pragma unroll
    for (int mt = 0; mt < 4; mt++) {
#pragma unroll
        for (int h = 0; h < 2; h++) {
            int node = node0 + wm * 64 + mt * 16 + tq + h * 8;
            if (node >= NN) continue;
#pragma unroll
            for (int nt = 0; nt < 4; nt++) {
                int col = wn * 32 + nt * 8 + tr * 2;
                float v0 = acc[mt][nt][h * 2 + 0] * B_INV + sbias[col];
                float v1 = acc[mt][nt][h * 2 + 1] * B_INV + sbias[col + 1];
                if (relu) { v0 = fmaxf(v0, 0.f); v1 = fmaxf(v1, 0.f); }
                if (wsplit) {
                    *(unsigned short*)(NU + (size_t)node * 256 + col) =
                        f2e4m3x2(v1, v0);
                } else {
                    *(float2*)(OUT + (size_t)node * FD + col) = make_float2(v0, v1);
                }
            }
        }
    }
}

// ---------------- fused pooling + readout (block = graph) --------------------
__global__ void k_poolhead(const float* __restrict__ H, const int* __restrict__ batch,
                           const float* __restrict__ gfeat,
                           const float* __restrict__ Wg, const float* __restrict__ bg,
                           const float* __restrict__ Wo, const float* __restrict__ bo,
                           float* __restrict__ out) {
    __shared__ int srange[2];
    __shared__ float flat[3 * FD];
    __shared__ float logits[2];
    int g = blockIdx.x, o = threadIdx.x;             // 128 threads
    if (o == 0) {
        int lo = 0, hi = NN;
        while (lo < hi) { int m = (lo + hi) >> 1; if (batch[m] < g) lo = m + 1; else hi = m; }
        srange[0] = lo;
        lo = 0; hi = NN;
        while (lo < hi) { int m = (lo + hi) >> 1; if (batch[m] <= g) lo = m + 1; else hi = m; }
        srange[1] = lo;
    }
    __syncthreads();
    int s0 = srange[0], s1 = srange[1];
    float sum = 0.f, mx = -INFINITY;
    int n = s0;
    for (; n + 3 < s1; n += 4) {
        float v0 = H[(size_t)(n + 0) * FD + o];
        float v1 = H[(size_t)(n + 1) * FD + o];
        float v2 = H[(size_t)(n + 2) * FD + o];
        float v3 = H[(size_t)(n + 3) * FD + o];
        sum += (v0 + v1) + (v2 + v3);
        mx = fmaxf(mx, fmaxf(fmaxf(v0, v1), fmaxf(v2, v3)));
    }
    for (; n < s1; n++) {
        float v = H[(size_t)n * FD + o];
        sum += v;
        mx = fmaxf(mx, v);
    }
    float cnt = fmaxf((float)(s1 - s0), 1.f);
    flat[o]      = sum / cnt;
    flat[FD + o] = mx;
    float acc = bg[o];
#pragma unroll
    for (int k = 0; k < GF; k++) acc += gfeat[g * GF + k] * Wg[k * FD + o];
    flat[2 * FD + o] = acc;
    __syncthreads();
    if (o < 2) {
        float l = bo[o];
        for (int j = 0; j < 3 * FD; j++) l += flat[j] * Wo[j * 2 + o];
        logits[o] = l;
    }
    __syncthreads();
    if (o < 2) {
        float mm  = fmaxf(logits[0], logits[1]);
        float lse = mm + logf(expf(logits[0] - mm) + expf(logits[1] - mm));
        out[g * 2 + o] = logits[o] - lse;
    }
}

// ---------------- launch -----------------------------------------------------
extern "C" void kernel_launch(void* const* d_in, const int* in_sizes, int n_in,
                              void* d_out, int out_size) {
    const float* x     = (const float*)d_in[0];
    const int*   edges = (const int*)  d_in[1];
    const int*   batch = (const int*)  d_in[2];
    const float* gfeat = (const float*)d_in[3];
    const float* Wl0   = (const float*)d_in[4];
    const float* bl0   = (const float*)d_in[5];
    const float* Wr0   = (const float*)d_in[6];
    const float* Wl1   = (const float*)d_in[7];
    const float* bl1   = (const float*)d_in[8];
    const float* Wr1   = (const float*)d_in[9];
    const float* Wg    = (const float*)d_in[10];
    const float* bg    = (const float*)d_in[11];
    const float* Wo    = (const float*)d_in[12];
    const float* bo    = (const float*)d_in[13];
    float* out = (float*)d_out;

    cudaFuncSetAttribute(k_gemm, cudaFuncAttributeMaxDynamicSharedMemorySize,
                         GEMM_SMEM);

    unsigned char *pU, *pB;
    float *p_h1;
    cudaGetSymbolAddress((void**)&pU, g_U);
    cudaGetSymbolAddress((void**)&pB, g_B);
    cudaGetSymbolAddress((void**)&p_h1, g_h1);

    const int scan_nb = (NN + SCAN_B - 1) / SCAN_B;   // 98
    const int gemm_nb = (NN + 127) / 128;             // 782

    k_prep<<<(NN * 32 + 255) / 256, 256>>>(x, Wr0, Wl0, Wr1, Wl1);
    k_hist<<<(NE + 255) / 256, 256>>>(edges);
    k_scan<<<scan_nb, SCAN_B>>>();
    k_fillcol<<<(NE + 255) / 256, 256>>>(edges);

    // layer 0: gather e4m3 x (U cols 0..127); GEMM writes h0 e4m3 in place
    k_aggregate<<<(NN + 7) / 8, 256>>>();
    k_gemm<<<gemm_nb, 256, GEMM_SMEM>>>(pU, pB, bl0, nullptr, pU, 1, 1);
    // layer 1: gather e4m3 h0; GEMM writes fp32 h1
    k_aggregate<<<(NN + 7) / 8, 256>>>();
    k_gemm<<<gemm_nb, 256, GEMM_SMEM>>>(pU, pB + 32768, bl1, p_h1, nullptr, 0, 0);

    // fused pooling + head
    k_poolhead<<<NG, FD>>>(p_h1, batch, gfeat, Wg, bg, Wo, bo, out);
}

// round 13
// speedup vs baseline: 1.0699x; 1.0699x over previous
#include <cuda_runtime.h>
#include <cuda_fp16.h>
#include <cstdint>
#include <math.h>

#define NN 100000
#define NE 1600000
#define FD 128
#define NG 128
#define GF 32

#define B_SCALE 32.0f
#define B_INV   (1.0f / 32.0f)

// ---------------- scratch (device globals; no allocations allowed) ----------
// INVARIANT: g_deg is all-zero at kernel_launch entry (zero-init at load;
// k_scan re-zeroes after consuming). g_scnt/g_sready likewise (reset in
// k_fillcol after the scan's spinners have exited).
__device__ __align__(16) unsigned char g_U[(size_t)NN * 256]; // [X|AGG] e4m3
__device__ __align__(16) unsigned char g_B[2 * 128 * 256];    // W^T e4m3 (x32)
__device__ __align__(16) float g_h1[(size_t)NN * FD];
__device__ int g_deg[NN];
__device__ int g_rowptr[NN];          // post-fillcol: rowptr[i] = end of row i
__device__ int g_col[NE];
__device__ int g_bsum[128];
__device__ int g_bpre[128];
__device__ int g_scnt;
__device__ int g_sready;

// ---------------- small helpers ---------------------------------------------
// pack: byte0 = lo, byte1 = hi
__device__ __forceinline__ unsigned short f2e4m3x2(float hi, float lo) {
    unsigned short r;
    asm("cvt.rn.satfinite.e4m3x2.f32 %0, %1, %2;" : "=h"(r) : "f"(hi), "f"(lo));
    return r;
}
__device__ __forceinline__ float2 e4m3x2f2(unsigned short u) {
    uint32_t h2;
    asm("cvt.rn.f16x2.e4m3x2 %0, %1;" : "=r"(h2) : "h"(u));
    return __half22float2(*(__half2*)&h2);
}

__device__ __forceinline__ uint32_t smem_u32(const void* p) {
    uint32_t a;
    asm("{ .reg .u64 t; cvta.to.shared.u64 t, %1; cvt.u32.u64 %0, t; }"
        : "=r"(a) : "l"(p));
    return a;
}

__device__ __forceinline__ void ldsm4(uint32_t* r, uint32_t addr) {
    asm volatile("ldmatrix.sync.aligned.m8n8.x4.shared.b16 {%0,%1,%2,%3}, [%4];"
                 : "=r"(r[0]), "=r"(r[1]), "=r"(r[2]), "=r"(r[3]) : "r"(addr));
}
__device__ __forceinline__ void ldsm2(uint32_t* r, uint32_t addr) {
    asm volatile("ldmatrix.sync.aligned.m8n8.x2.shared.b16 {%0,%1}, [%2];"
                 : "=r"(r[0]), "=r"(r[1]) : "r"(addr));
}
__device__ __forceinline__ void mma_fp8(float* c, const uint32_t* a, const uint32_t* b) {
    asm volatile(
        "mma.sync.aligned.m16n8k32.row.col.f32.e4m3.e4m3.f32 "
        "{%0,%1,%2,%3}, {%4,%5,%6,%7}, {%8,%9}, {%0,%1,%2,%3};"
        : "+f"(c[0]), "+f"(c[1]), "+f"(c[2]), "+f"(c[3])
        : "r"(a[0]), "r"(a[1]), "r"(a[2]), "r"(a[3]), "r"(b[0]), "r"(b[1]));
}

// ---------------- fused prep: x fp8 + weights fp8 + edge histogram ----------
__global__ void k_prep(const float* __restrict__ X, const int* __restrict__ edges,
                       const float* __restrict__ Wr0, const float* __restrict__ Wl0,
                       const float* __restrict__ Wr1, const float* __restrict__ Wl1) {
    int i = blockIdx.x * 256 + threadIdx.x;          // 3.2M threads
    if (i < NN * 32) {                               // x -> e4m3 U cols 0..127
        float4 v = ((const float4*)X)[i];
        int node = i >> 5, q = (i & 31) * 4;
        uint32_t lo = f2e4m3x2(v.y, v.x);
        uint32_t hi = f2e4m3x2(v.w, v.z);
        *(uint32_t*)(g_U + (size_t)node * 256 + q) = lo | (hi << 16);
    }
    if (i < 65536) {                                 // weights -> e4m3 (x32)
        int L = i >> 15;
        int rem = i & 32767;
        int k = rem >> 7, n = rem & 127;
        const float* Wr = L ? Wr1 : Wr0;
        const float* Wl = L ? Wl1 : Wl0;
        float v = ((k < FD) ? Wr[k * FD + n] : Wl[(k - FD) * FD + n]) * B_SCALE;
        unsigned short p = f2e4m3x2(0.f, v);
        g_B[L * 32768 + n * 256 + k] = (unsigned char)(p & 0xFF);
    }
    if (i < NE)                                      // histogram (deg starts 0)
        atomicAdd(&g_deg[edges[NE + i]], 1);
}

// ---------------- CSR: single-kernel exclusive scan (publish + wait) ---------
#define SCAN_B 1024
__global__ void k_scan() {
    __shared__ int sm[SCAN_B];
    __shared__ int bpre;
    int bid = blockIdx.x, tid = threadIdx.x;
    int i = bid * SCAN_B + tid;
    int v = 0;
    if (i < NN) {
        v = g_deg[i];
        g_deg[i] = 0;                                // restore invariant
    }
    sm[tid] = v;
    __syncthreads();
    for (int off = 1; off < SCAN_B; off <<= 1) {
        int t = (tid >= off) ? sm[tid - off] : 0;
        __syncthreads();
        sm[tid] += t;
        __syncthreads();
    }
    if (tid == SCAN_B - 1) {
        g_bsum[bid] = sm[SCAN_B - 1];
        __threadfence();
        int d = atomicAdd(&g_scnt, 1);
        if (d == (int)gridDim.x - 1) {               // last block: scan aggregates
            int acc = 0;
#pragma unroll 4
            for (int j = 0; j < (int)gridDim.x; j++) {
                int t = g_bsum[j];
                g_bpre[j] = acc;
                acc += t;
            }
            __threadfence();
            atomicExch(&g_sready, 1);
        }
    }
    if (tid == 0) {
        while (*((volatile int*)&g_sready) == 0) __nanosleep(64);
        bpre = *((volatile int*)&g_bpre[bid]);
    }
    __syncthreads();
    if (i < NN) g_rowptr[i] = sm[tid] - v + bpre;    // exclusive prefix
}

// ---------------- CSR: fill columns (bumps rowptr to end offsets) -----------
__global__ void k_fillcol(const int* __restrict__ edges) {
    int e = blockIdx.x * blockDim.x + threadIdx.x;
    if (e == 0) { g_scnt = 0; g_sready = 0; }        // reset for next call
    if (e < NE) {
        int t = edges[NE + e];
        int p = atomicAdd(&g_rowptr[t], 1);
        g_col[p] = edges[e];
    }
}

// ---------------- neighbor mean aggregation (e4m3 gather) --------------------
// After fillcol: beg = (node ? rowptr[node-1] : 0), end = rowptr[node].
__global__ void k_aggregate() {
    int node = blockIdx.x * 8 + (threadIdx.x >> 5);
    int lane = threadIdx.x & 31;
    if (node >= NN) return;
    int beg = node ? g_rowptr[node - 1] : 0;
    int end = g_rowptr[node];
    const uint32_t* Hv = (const uint32_t*)g_U;       // 4 fp8 per lane
    float4 s = make_float4(0.f, 0.f, 0.f, 0.f);
    int e = beg;
    for (; e + 3 < end; e += 4) {
        int i0 = g_col[e], i1 = g_col[e + 1], i2 = g_col[e + 2], i3 = g_col[e + 3];
        uint32_t u0 = Hv[(size_t)i0 * 64 + lane];
        uint32_t u1 = Hv[(size_t)i1 * 64 + lane];
        uint32_t u2 = Hv[(size_t)i2 * 64 + lane];
        uint32_t u3 = Hv[(size_t)i3 * 64 + lane];
        float2 a0 = e4m3x2f2((unsigned short)u0), a1 = e4m3x2f2((unsigned short)(u0 >> 16));
        float2 b0 = e4m3x2f2((unsigned short)u1), b1 = e4m3x2f2((unsigned short)(u1 >> 16));
        float2 c0 = e4m3x2f2((unsigned short)u2), c1 = e4m3x2f2((unsigned short)(u2 >> 16));
        float2 d0 = e4m3x2f2((unsigned short)u3), d1 = e4m3x2f2((unsigned short)(u3 >> 16));
        s.x += (a0.x + b0.x) + (c0.x + d0.x);
        s.y += (a0.y + b0.y) + (c0.y + d0.y);
        s.z += (a1.x + b1.x) + (c1.x + d1.x);
        s.w += (a1.y + b1.y) + (c1.y + d1.y);
    }
    for (; e < end; e++) {
        uint32_t u = Hv[(size_t)g_col[e] * 64 + lane];
        float2 f0 = e4m3x2f2((unsigned short)u), f1 = e4m3x2f2((unsigned short)(u >> 16));
        s.x += f0.x; s.y += f0.y; s.z += f1.x; s.w += f1.y;
    }
    float sc = 1.f / fmaxf((float)(end - beg), 1.f);
    uint32_t lo = f2e4m3x2(s.y * sc, s.x * sc);
    uint32_t hi = f2e4m3x2(s.w * sc, s.z * sc);
    *(uint32_t*)(g_U + (size_t)node * 256 + 128 + lane * 4) = lo | (hi << 16);
}

// ---------------- mma.sync GEMM: e4m3 A x e4m3 B (m16n8k32) -----------------
// CTA: 128 nodes x 128 outs; 8 warps 2(M)x4(N); warp tile 64x32.
// K = 256 fp8 bytes, 2 chunks of 128B; ks step = 32 bytes (k32).
#define TPB 144
#define TILE_B (128 * TPB)                   // 18432 bytes per tile
#define GEMM_SMEM (2 * TILE_B + 512)

__device__ __forceinline__ void load_chunk(unsigned char* dst,
                                           const unsigned char* __restrict__ src,
                                           int row0, int rowmax, int kofs) {
    for (int i = threadIdx.x; i < 1024; i += 256) {  // uint4 units (16 fp8)
        int r = i >> 3, q = i & 7;
        int gr = row0 + r;
        uint4 v = make_uint4(0, 0, 0, 0);
        if (gr < rowmax) v = *(const uint4*)(src + (size_t)gr * 256 + kofs + q * 16);
        *(uint4*)(dst + r * TPB + q * 16) = v;
    }
}

__global__ __launch_bounds__(256, 2) void k_gemm(
    const unsigned char* __restrict__ U, const unsigned char* __restrict__ B,
    const float* __restrict__ bias, float* __restrict__ OUT,
    unsigned char* __restrict__ NU, int relu, int wsplit)
{
    extern __shared__ char smem[];
    unsigned char* sU = (unsigned char*)smem;
    unsigned char* sB = (unsigned char*)(smem + TILE_B);
    float* sbias = (float*)(smem + 2 * TILE_B);

    const int tid = threadIdx.x, wid = tid >> 5, lid = tid & 31;
    const int wm = wid >> 2, wn = wid & 3;
    const int node0 = blockIdx.x * 128;

    if (tid < FD) sbias[tid] = bias[tid];

    float acc[4][4][4];
#pragma unroll
    for (int mt = 0; mt < 4; mt++)
#pragma unroll
        for (int nt = 0; nt < 4; nt++)
#pragma unroll
            for (int j = 0; j < 4; j++) acc[mt][nt][j] = 0.f;

    uint32_t aU = smem_u32(sU), aB = smem_u32(sB);
    const uint32_t a_lane = (uint32_t)((lid & 15) * TPB + ((lid >> 4) << 4));
    const uint32_t b_lane = (uint32_t)((lid & 7) * TPB + (((lid >> 3) & 1) << 4));

    for (int c = 0; c < 2; c++) {
        load_chunk(sU, U, node0, NN, c * 128);
        load_chunk(sB, B, 0, 128, c * 128);
        __syncthreads();
#pragma unroll
        for (int ks = 0; ks < 4; ks++) {
            uint32_t ah[4][4];
#pragma unroll
            for (int mt = 0; mt < 4; mt++) {
                uint32_t roff = (uint32_t)((wm * 64 + mt * 16) * TPB + ks * 32);
                ldsm4(ah[mt], aU + roff + a_lane);
            }
#pragma unroll
            for (int nt = 0; nt < 4; nt++) {
                uint32_t bb[2];
                uint32_t roff = (uint32_t)((wn * 32 + nt * 8) * TPB + ks * 32);
                ldsm2(bb, aB + roff + b_lane);
#pragma unroll
                for (int mt = 0; mt < 4; mt++)
                    mma_fp8(acc[mt][nt], ah[mt], bb);
            }
        }
        __syncthreads();
    }

    // epilogue: c-fragment (row = t/4 [+8], col = 2*(t%4) [+1])
    const int tq = lid >> 2, tr = lid & 3;
#pragma unroll
    for (int mt = 0; mt < 4; mt++) {
#pragma unroll
        for (int h = 0; h < 2; h++) {
            int node = node0 + wm * 64 + mt * 16 + tq + h * 8;
            if (node >= NN) continue;
#pragma unroll
            for (int nt = 0; nt < 4; nt++) {
                int col = wn * 32 + nt * 8 + tr * 2;
                float v0 = acc[mt][nt][h * 2 + 0] * B_INV + sbias[col];
                float v1 = acc[mt][nt][h * 2 + 1] * B_INV + sbias[col + 1];
                if (relu) { v0 = fmaxf(v0, 0.f); v1 = fmaxf(v1, 0.f); }
                if (wsplit) {
                    *(unsigned short*)(NU + (size_t)node * 256 + col) =
                        f2e4m3x2(v1, v0);
                } else {
                    *(float2*)(OUT + (size_t)node * FD + col) = make_float2(v0, v1);
                }
            }
        }
    }
}

// ---------------- fused pooling + readout (block = graph, 256 threads) -------
__global__ void k_poolhead(const float* __restrict__ H, const int* __restrict__ batch,
                           const float* __restrict__ gfeat,
                           const float* __restrict__ Wg, const float* __restrict__ bg,
                           const float* __restrict__ Wo, const float* __restrict__ bo,
                           float* __restrict__ out) {
    __shared__ int srange[2];
    __shared__ float psum[2][FD];
    __shared__ float pmax[2][FD];
    __shared__ float flat[3 * FD];
    __shared__ float logits[2];
    int g = blockIdx.x, tid = threadIdx.x;           // 256 threads
    int o = tid & 127, half = tid >> 7;
    if (tid == 0) {
        int lo = 0, hi = NN;
        while (lo < hi) { int m = (lo + hi) >> 1; if (batch[m] < g) lo = m + 1; else hi = m; }
        srange[0] = lo;
        lo = 0; hi = NN;
        while (lo < hi) { int m = (lo + hi) >> 1; if (batch[m] <= g) lo = m + 1; else hi = m; }
        srange[1] = lo;
    }
    __syncthreads();
    int s0 = srange[0], s1 = srange[1];
    float sum = 0.f, mx = -INFINITY;
    int n = s0 + half;
    for (; n + 6 < s1; n += 8) {                     // 4 rows per stream
        float v0 = H[(size_t)(n + 0) * FD + o];
        float v1 = H[(size_t)(n + 2) * FD + o];
        float v2 = H[(size_t)(n + 4) * FD + o];
        float v3 = H[(size_t)(n + 6) * FD + o];
        sum += (v0 + v1) + (v2 + v3);
        mx = fmaxf(mx, fmaxf(fmaxf(v0, v1), fmaxf(v2, v3)));
    }
    for (; n < s1; n += 2) {
        float v = H[(size_t)n * FD + o];
        sum += v;
        mx = fmaxf(mx, v);
    }
    psum[half][o] = sum;
    pmax[half][o] = mx;
    __syncthreads();
    if (half == 0) {
        float cnt = fmaxf((float)(s1 - s0), 1.f);
        flat[o]      = (psum[0][o] + psum[1][o]) / cnt;
        flat[FD + o] = fmaxf(pmax[0][o], pmax[1][o]);
        float acc = bg[o];
#pragma unroll
        for (int k = 0; k < GF; k++) acc += gfeat[g * GF + k] * Wg[k * FD + o];
        flat[2 * FD + o] = acc;
    }
    __syncthreads();
    if (tid < 2) {
        float l = bo[tid];
        for (int j = 0; j < 3 * FD; j++) l += flat[j] * Wo[j * 2 + tid];
        logits[tid] = l;
    }
    __syncthreads();
    if (tid < 2) {
        float mm  = fmaxf(logits[0], logits[1]);
        float lse = mm + logf(expf(logits[0] - mm) + expf(logits[1] - mm));
        out[g * 2 + tid] = logits[tid] - lse;
    }
}

// ---------------- launch -----------------------------------------------------
extern "C" void kernel_launch(void* const* d_in, const int* in_sizes, int n_in,
                              void* d_out, int out_size) {
    const float* x     = (const float*)d_in[0];
    const int*   edges = (const int*)  d_in[1];
    const int*   batch = (const int*)  d_in[2];
    const float* gfeat = (const float*)d_in[3];
    const float* Wl0   = (const float*)d_in[4];
    const float* bl0   = (const float*)d_in[5];
    const float* Wr0   = (const float*)d_in[6];
    const float* Wl1   = (const float*)d_in[7];
    const float* bl1   = (const float*)d_in[8];
    const float* Wr1   = (const float*)d_in[9];
    const float* Wg    = (const float*)d_in[10];
    const float* bg    = (const float*)d_in[11];
    const float* Wo    = (const float*)d_in[12];
    const float* bo    = (const float*)d_in[13];
    float* out = (float*)d_out;

    cudaFuncSetAttribute(k_gemm, cudaFuncAttributeMaxDynamicSharedMemorySize,
                         GEMM_SMEM);

    unsigned char *pU, *pB;
    float *p_h1;
    cudaGetSymbolAddress((void**)&pU, g_U);
    cudaGetSymbolAddress((void**)&pB, g_B);
    cudaGetSymbolAddress((void**)&p_h1, g_h1);

    const int scan_nb = (NN + SCAN_B - 1) / SCAN_B;   // 98
    const int gemm_nb = (NN + 127) / 128;             // 782

    k_prep<<<(NN * 32 + 255) / 256, 256>>>(x, edges, Wr0, Wl0, Wr1, Wl1);
    k_scan<<<scan_nb, SCAN_B>>>();
    k_fillcol<<<(NE + 255) / 256, 256>>>(edges);

    // layer 0: gather e4m3 x (U cols 0..127); GEMM writes h0 e4m3 in place
    k_aggregate<<<(NN + 7) / 8, 256>>>();
    k_gemm<<<gemm_nb, 256, GEMM_SMEM>>>(pU, pB, bl0, nullptr, pU, 1, 1);
    // layer 1: gather e4m3 h0; GEMM writes fp32 h1
    k_aggregate<<<(NN + 7) / 8, 256>>>();
    k_gemm<<<gemm_nb, 256, GEMM_SMEM>>>(pU, pB + 32768, bl1, p_h1, nullptr, 0, 0);

    // fused pooling + head
    k_poolhead<<<NG, 256>>>(p_h1, batch, gfeat, Wg, bg, Wo, bo, out);
}

// round 14
// speedup vs baseline: 1.0867x; 1.0157x over previous
#include <cuda_runtime.h>
#include <cuda_fp16.h>
#include <cstdint>
#include <math.h>

#define NN 100000
#define NE 1600000
#define FD 128
#define NG 128
#define GF 32

#define B_SCALE 32.0f
#define B_INV   (1.0f / 32.0f)

// ---------------- scratch (device globals; no allocations allowed) ----------
// INVARIANT: g_deg is all-zero at kernel_launch entry (zero-init at load;
// k_scan re-zeroes after consuming). g_scnt/g_sready likewise (reset in
// k_fillcol after the scan's spinners have exited).
__device__ __align__(16) unsigned char g_U[(size_t)NN * 256]; // [X|AGG] e4m3
__device__ __align__(16) unsigned char g_B[2 * 128 * 256];    // W^T e4m3 (x32)
__device__ __align__(16) float g_h1[(size_t)NN * FD];
__device__ int g_deg[NN];
__device__ int g_rowptr[NN];          // post-fillcol: rowptr[i] = end of row i
__device__ int g_col[NE];
__device__ int g_bsum[128];
__device__ int g_bpre[128];
__device__ int g_scnt;
__device__ int g_sready;

// ---------------- small helpers ---------------------------------------------
// pack: byte0 = lo, byte1 = hi
__device__ __forceinline__ unsigned short f2e4m3x2(float hi, float lo) {
    unsigned short r;
    asm("cvt.rn.satfinite.e4m3x2.f32 %0, %1, %2;" : "=h"(r) : "f"(hi), "f"(lo));
    return r;
}
__device__ __forceinline__ __half2 e4m3x2h2(unsigned short u) {
    uint32_t h2;
    asm("cvt.rn.f16x2.e4m3x2 %0, %1;" : "=r"(h2) : "h"(u));
    return *(__half2*)&h2;
}

__device__ __forceinline__ uint32_t smem_u32(const void* p) {
    uint32_t a;
    asm("{ .reg .u64 t; cvta.to.shared.u64 t, %1; cvt.u32.u64 %0, t; }"
        : "=r"(a) : "l"(p));
    return a;
}

__device__ __forceinline__ void ldsm4(uint32_t* r, uint32_t addr) {
    asm volatile("ldmatrix.sync.aligned.m8n8.x4.shared.b16 {%0,%1,%2,%3}, [%4];"
                 : "=r"(r[0]), "=r"(r[1]), "=r"(r[2]), "=r"(r[3]) : "r"(addr));
}
__device__ __forceinline__ void ldsm2(uint32_t* r, uint32_t addr) {
    asm volatile("ldmatrix.sync.aligned.m8n8.x2.shared.b16 {%0,%1}, [%2];"
                 : "=r"(r[0]), "=r"(r[1]) : "r"(addr));
}
__device__ __forceinline__ void mma_fp8(float* c, const uint32_t* a, const uint32_t* b) {
    asm volatile(
        "mma.sync.aligned.m16n8k32.row.col.f32.e4m3.e4m3.f32 "
        "{%0,%1,%2,%3}, {%4,%5,%6,%7}, {%8,%9}, {%0,%1,%2,%3};"
        : "+f"(c[0]), "+f"(c[1]), "+f"(c[2]), "+f"(c[3])
        : "r"(a[0]), "r"(a[1]), "r"(a[2]), "r"(a[3]), "r"(b[0]), "r"(b[1]));
}

// ---------------- fused prep: x fp8 + weights fp8 + edge histogram ----------
__global__ void k_prep(const float* __restrict__ X, const int* __restrict__ edges,
                       const float* __restrict__ Wr0, const float* __restrict__ Wl0,
                       const float* __restrict__ Wr1, const float* __restrict__ Wl1) {
    int i = blockIdx.x * 256 + threadIdx.x;          // 3.2M threads
    if (i < NN * 32) {                               // x -> e4m3 U cols 0..127
        float4 v = ((const float4*)X)[i];
        int node = i >> 5, q = (i & 31) * 4;
        uint32_t lo = f2e4m3x2(v.y, v.x);
        uint32_t hi = f2e4m3x2(v.w, v.z);
        *(uint32_t*)(g_U + (size_t)node * 256 + q) = lo | (hi << 16);
    }
    if (i < 65536) {                                 // weights -> e4m3 (x32)
        int L = i >> 15;
        int rem = i & 32767;
        int k = rem >> 7, n = rem & 127;
        const float* Wr = L ? Wr1 : Wr0;
        const float* Wl = L ? Wl1 : Wl0;
        float v = ((k < FD) ? Wr[k * FD + n] : Wl[(k - FD) * FD + n]) * B_SCALE;
        unsigned short p = f2e4m3x2(0.f, v);
        g_B[L * 32768 + n * 256 + k] = (unsigned char)(p & 0xFF);
    }
    if (i < NE)                                      // histogram (deg starts 0)
        atomicAdd(&g_deg[edges[NE + i]], 1);
}

// ---------------- CSR: single-kernel exclusive scan (publish + wait) ---------
#define SCAN_B 1024
__global__ void k_scan() {
    __shared__ int sm[SCAN_B];
    __shared__ int bpre;
    int bid = blockIdx.x, tid = threadIdx.x;
    int i = bid * SCAN_B + tid;
    int v = 0;
    if (i < NN) {
        v = g_deg[i];
        g_deg[i] = 0;                                // restore invariant
    }
    sm[tid] = v;
    __syncthreads();
    for (int off = 1; off < SCAN_B; off <<= 1) {
        int t = (tid >= off) ? sm[tid - off] : 0;
        __syncthreads();
        sm[tid] += t;
        __syncthreads();
    }
    if (tid == SCAN_B - 1) {
        g_bsum[bid] = sm[SCAN_B - 1];
        __threadfence();
        int d = atomicAdd(&g_scnt, 1);
        if (d == (int)gridDim.x - 1) {               // last block: scan aggregates
            int acc = 0;
#pragma unroll 4
            for (int j = 0; j < (int)gridDim.x; j++) {
                int t = g_bsum[j];
                g_bpre[j] = acc;
                acc += t;
            }
            __threadfence();
            atomicExch(&g_sready, 1);
        }
    }
    if (tid == 0) {
        while (*((volatile int*)&g_sready) == 0) __nanosleep(64);
        bpre = *((volatile int*)&g_bpre[bid]);
    }
    __syncthreads();
    if (i < NN) g_rowptr[i] = sm[tid] - v + bpre;    // exclusive prefix
}

// ---------------- CSR: fill columns (bumps rowptr to end offsets) -----------
__global__ void k_fillcol(const int* __restrict__ edges) {
    int e = blockIdx.x * blockDim.x + threadIdx.x;
    if (e == 0) { g_scnt = 0; g_sready = 0; }        // reset for next call
    if (e < NE) {
        int t = edges[NE + e];
        int p = atomicAdd(&g_rowptr[t], 1);
        g_col[p] = edges[e];
    }
}

// ---------------- neighbor mean aggregation (e4m3 gather, fp16 accum) --------
// After fillcol: beg = (node ? rowptr[node-1] : 0), end = rowptr[node].
// Per neighbor per lane: 1 LDG + 2 cvt + 2 HADD2 (fp16 accumulation).
__global__ void k_aggregate() {
    int node = blockIdx.x * 8 + (threadIdx.x >> 5);
    int lane = threadIdx.x & 31;
    if (node >= NN) return;
    int beg = node ? g_rowptr[node - 1] : 0;
    int end = g_rowptr[node];
    const uint32_t* Hv = (const uint32_t*)g_U;       // 4 fp8 per lane
    __half2 z = __float2half2_rn(0.f);
    __half2 sa0 = z, sa1 = z, sb0 = z, sb1 = z;      // 2 independent pairs
    int e = beg;
    for (; e + 1 < end; e += 2) {
        uint32_t u0 = Hv[(size_t)g_col[e] * 64 + lane];
        uint32_t u1 = Hv[(size_t)g_col[e + 1] * 64 + lane];
        sa0 = __hadd2(sa0, e4m3x2h2((unsigned short)u0));
        sa1 = __hadd2(sa1, e4m3x2h2((unsigned short)(u0 >> 16)));
        sb0 = __hadd2(sb0, e4m3x2h2((unsigned short)u1));
        sb1 = __hadd2(sb1, e4m3x2h2((unsigned short)(u1 >> 16)));
    }
    if (e < end) {
        uint32_t u = Hv[(size_t)g_col[e] * 64 + lane];
        sa0 = __hadd2(sa0, e4m3x2h2((unsigned short)u));
        sa1 = __hadd2(sa1, e4m3x2h2((unsigned short)(u >> 16)));
    }
    float2 f0 = __half22float2(sa0), g0 = __half22float2(sb0);
    float2 f1 = __half22float2(sa1), g1 = __half22float2(sb1);
    float sc = 1.f / fmaxf((float)(end - beg), 1.f);
    uint32_t lo = f2e4m3x2((f0.y + g0.y) * sc, (f0.x + g0.x) * sc);
    uint32_t hi = f2e4m3x2((f1.y + g1.y) * sc, (f1.x + g1.x) * sc);
    *(uint32_t*)(g_U + (size_t)node * 256 + 128 + lane * 4) = lo | (hi << 16);
}

// ---------------- mma.sync GEMM: e4m3 A x e4m3 B (m16n8k32) -----------------
// CTA: 128 nodes x 128 outs; 8 warps 2(M)x4(N); warp tile 64x32.
// K = 256 fp8 bytes, 2 chunks of 128B; ks step = 32 bytes (k32).
#define TPB 144
#define TILE_B (128 * TPB)                   // 18432 bytes per tile
#define GEMM_SMEM (2 * TILE_B + 512)

__device__ __forceinline__ void load_chunk(unsigned char* dst,
                                           const unsigned char* __restrict__ src,
                                           int row0, int rowmax, int kofs) {
    for (int i = threadIdx.x; i < 1024; i += 256) {  // uint4 units (16 fp8)
        int r = i >> 3, q = i & 7;
        int gr = row0 + r;
        uint4 v = make_uint4(0, 0, 0, 0);
        if (gr < rowmax) v = *(const uint4*)(src + (size_t)gr * 256 + kofs + q * 16);
        *(uint4*)(dst + r * TPB + q * 16) = v;
    }
}

__global__ __launch_bounds__(256, 2) void k_gemm(
    const unsigned char* __restrict__ U, const unsigned char* __restrict__ B,
    const float* __restrict__ bias, float* __restrict__ OUT,
    unsigned char* __restrict__ NU, int relu, int wsplit)
{
    extern __shared__ char smem[];
    unsigned char* sU = (unsigned char*)smem;
    unsigned char* sB = (unsigned char*)(smem + TILE_B);
    float* sbias = (float*)(smem + 2 * TILE_B);

    const int tid = threadIdx.x, wid = tid >> 5, lid = tid & 31;
    const int wm = wid >> 2, wn = wid & 3;
    const int node0 = blockIdx.x * 128;

    if (tid < FD) sbias[tid] = bias[tid];

    float acc[4][4][4];
#pragma unroll
    for (int mt = 0; mt < 4; mt++)
#pragma unroll
        for (int nt = 0; nt < 4; nt++)
#pragma unroll
            for (int j = 0; j < 4; j++) acc[mt][nt][j] = 0.f;

    uint32_t aU = smem_u32(sU), aB = smem_u32(sB);
    const uint32_t a_lane = (uint32_t)((lid & 15) * TPB + ((lid >> 4) << 4));
    const uint32_t b_lane = (uint32_t)((lid & 7) * TPB + (((lid >> 3) & 1) << 4));

    for (int c = 0; c < 2; c++) {
        load_chunk(sU, U, node0, NN, c * 128);
        load_chunk(sB, B, 0, 128, c * 128);
        __syncthreads();
#pragma unroll
        for (int ks = 0; ks < 4; ks++) {
            uint32_t ah[4][4];
#pragma unroll
            for (int mt = 0; mt < 4; mt++) {
                uint32_t roff = (uint32_t)((wm * 64 + mt * 16) * TPB + ks * 32);
                ldsm4(ah[mt], aU + roff + a_lane);
            }
#pragma unroll
            for (int nt = 0; nt < 4; nt++) {
                uint32_t bb[2];
                uint32_t roff = (uint32_t)((wn * 32 + nt * 8) * TPB + ks * 32);
                ldsm2(bb, aB + roff + b_lane);
#pragma unroll
                for (int mt = 0; mt < 4; mt++)
                    mma_fp8(acc[mt][nt], ah[mt], bb);
            }
        }
        __syncthreads();
    }

    // epilogue: c-fragment (row = t/4 [+8], col = 2*(t%4) [+1])
    const int tq = lid >> 2, tr = lid & 3;
#pragma unroll
    for (int mt = 0; mt < 4; mt++) {
#pragma unroll
        for (int h = 0; h < 2; h++) {
            int node = node0 + wm * 64 + mt * 16 + tq + h * 8;
            if (node >= NN) continue;
#pragma unroll
            for (int nt = 0; nt < 4; nt++) {
                int col = wn * 32 + nt * 8 + tr * 2;
                float v0 = acc[mt][nt][h * 2 + 0] * B_INV + sbias[col];
                float v1 = acc[mt][nt][h * 2 + 1] * B_INV + sbias[col + 1];
                if (relu) { v0 = fmaxf(v0, 0.f); v1 = fmaxf(v1, 0.f); }
                if (wsplit) {
                    *(unsigned short*)(NU + (size_t)node * 256 + col) =
                        f2e4m3x2(v1, v0);
                } else {
                    *(float2*)(OUT + (size_t)node * FD + col) = make_float2(v0, v1);
                }
            }
        }
    }
}

// ---------------- fused pooling + readout (block = graph, 256 threads) -------
__global__ void k_poolhead(const float* __restrict__ H, const int* __restrict__ batch,
                           const float* __restrict__ gfeat,
                           const float* __restrict__ Wg, const float* __restrict__ bg,
                           const float* __restrict__ Wo, const float* __restrict__ bo,
                           float* __restrict__ out) {
    __shared__ int srange[2];
    __shared__ float psum[2][FD];
    __shared__ float pmax[2][FD];
    __shared__ float flat[3 * FD];
    __shared__ float logits[2];
    int g = blockIdx.x, tid = threadIdx.x;           // 256 threads
    int o = tid & 127, half = tid >> 7;
    if (tid == 0) {
        int lo = 0, hi = NN;
        while (lo < hi) { int m = (lo + hi) >> 1; if (batch[m] < g) lo = m + 1; else hi = m; }
        srange[0] = lo;
        lo = 0; hi = NN;
        while (lo < hi) { int m = (lo + hi) >> 1; if (batch[m] <= g) lo = m + 1; else hi = m; }
        srange[1] = lo;
    }
    __syncthreads();
    int s0 = srange[0], s1 = srange[1];
    float sum = 0.f, mx = -INFINITY;
    int n = s0 + half;
    for (; n + 6 < s1; n += 8) {                     // 4 rows per stream
        float v0 = H[(size_t)(n + 0) * FD + o];
        float v1 = H[(size_t)(n + 2) * FD + o];
        float v2 = H[(size_t)(n + 4) * FD + o];
        float v3 = H[(size_t)(n + 6) * FD + o];
        sum += (v0 + v1) + (v2 + v3);
        mx = fmaxf(mx, fmaxf(fmaxf(v0, v1), fmaxf(v2, v3)));
    }
    for (; n < s1; n += 2) {
        float v = H[(size_t)n * FD + o];
        sum += v;
        mx = fmaxf(mx, v);
    }
    psum[half][o] = sum;
    pmax[half][o] = mx;
    __syncthreads();
    if (half == 0) {
        float cnt = fmaxf((float)(s1 - s0), 1.f);
        flat[o]      = (psum[0][o] + psum[1][o]) / cnt;
        flat[FD + o] = fmaxf(pmax[0][o], pmax[1][o]);
        float acc = bg[o];
#pragma unroll
        for (int k = 0; k < GF; k++) acc += gfeat[g * GF + k] * Wg[k * FD + o];
        flat[2 * FD + o] = acc;
    }
    __syncthreads();
    if (tid < 2) {
        float l = bo[tid];
        for (int j = 0; j < 3 * FD; j++) l += flat[j] * Wo[j * 2 + tid];
        logits[tid] = l;
    }
    __syncthreads();
    if (tid < 2) {
        float mm  = fmaxf(logits[0], logits[1]);
        float lse = mm + logf(expf(logits[0] - mm) + expf(logits[1] - mm));
        out[g * 2 + tid] = logits[tid] - lse;
    }
}

// ---------------- launch -----------------------------------------------------
extern "C" void kernel_launch(void* const* d_in, const int* in_sizes, int n_in,
                              void* d_out, int out_size) {
    const float* x     = (const float*)d_in[0];
    const int*   edges = (const int*)  d_in[1];
    const int*   batch = (const int*)  d_in[2];
    const float* gfeat = (const float*)d_in[3];
    const float* Wl0   = (const float*)d_in[4];
    const float* bl0   = (const float*)d_in[5];
    const float* Wr0   = (const float*)d_in[6];
    const float* Wl1   = (const float*)d_in[7];
    const float* bl1   = (const float*)d_in[8];
    const float* Wr1   = (const float*)d_in[9];
    const float* Wg    = (const float*)d_in[10];
    const float* bg    = (const float*)d_in[11];
    const float* Wo    = (const float*)d_in[12];
    const float* bo    = (const float*)d_in[13];
    float* out = (float*)d_out;

    cudaFuncSetAttribute(k_gemm, cudaFuncAttributeMaxDynamicSharedMemorySize,
                         GEMM_SMEM);

    unsigned char *pU, *pB;
    float *p_h1;
    cudaGetSymbolAddress((void**)&pU, g_U);
    cudaGetSymbolAddress((void**)&pB, g_B);
    cudaGetSymbolAddress((void**)&p_h1, g_h1);

    const int scan_nb = (NN + SCAN_B - 1) / SCAN_B;   // 98
    const int gemm_nb = (NN + 127) / 128;             // 782

    k_prep<<<(NN * 32 + 255) / 256, 256>>>(x, edges, Wr0, Wl0, Wr1, Wl1);
    k_scan<<<scan_nb, SCAN_B>>>();
    k_fillcol<<<(NE + 255) / 256, 256>>>(edges);

    // layer 0: gather e4m3 x (U cols 0..127); GEMM writes h0 e4m3 in place
    k_aggregate<<<(NN + 7) / 8, 256>>>();
    k_gemm<<<gemm_nb, 256, GEMM_SMEM>>>(pU, pB, bl0, nullptr, pU, 1, 1);
    // layer 1: gather e4m3 h0; GEMM writes fp32 h1
    k_aggregate<<<(NN + 7) / 8, 256>>>();
    k_gemm<<<gemm_nb, 256, GEMM_SMEM>>>(pU, pB + 32768, bl1, p_h1, nullptr, 0, 0);

    // fused pooling + head
    k_poolhead<<<NG, 256>>>(p_h1, batch, gfeat, Wg, bg, Wo, bo, out);
}